// round 10
// baseline (speedup 1.0000x reference)
#include <cuda_runtime.h>
#include <math.h>
#include <stdint.h>

#define EPSF 1e-5f

// ---------------- scratch (device globals) ----------------
__device__ float g_qkv[4194304];      // [128 bh][256 o][128 l]
__device__ float g_outraw[4194304];   // [128 bh][256 o][128 i]
__device__ float g_qkvStats[512];     // [256 ch][sum,sumsq]
__device__ float g_simStats[96];
__device__ float g_outStats[512];
__device__ float g_scaleQ[256];
__device__ float g_shiftQ[256];
__device__ float g_simScale[48];
__device__ float g_outScale[256];
__device__ float g_outShift[256];

__device__ __forceinline__ float warpSum(float v) {
#pragma unroll
    for (int o = 16; o > 0; o >>= 1) v += __shfl_xor_sync(0xffffffffu, v, o);
    return v;
}

// sum across the 8 lanes differing in bits 0..2 (tx groups in kA)
__device__ __forceinline__ float txSum(float v) {
    v += __shfl_xor_sync(0xffffffffu, v, 1);
    v += __shfl_xor_sync(0xffffffffu, v, 2);
    v += __shfl_xor_sync(0xffffffffu, v, 4);
    return v;
}

// reduce across lanes that differ only in bits 2..4 (rw groups, cl fixed)
__device__ __forceinline__ float rwSum(float v) {
    v += __shfl_xor_sync(0xffffffffu, v, 4);
    v += __shfl_xor_sync(0xffffffffu, v, 8);
    v += __shfl_xor_sync(0xffffffffu, v, 16);
    return v;
}

__device__ __forceinline__ uint32_t tf32r(float x) {
    uint32_t u;
    asm("cvt.rna.tf32.f32 %0, %1;" : "=r"(u) : "f"(x));
    return u;
}

__device__ __forceinline__ void mma8(float* c, const uint32_t* a, uint32_t b0, uint32_t b1) {
    asm volatile(
        "mma.sync.aligned.m16n8k8.row.col.f32.tf32.tf32.f32 "
        "{%0,%1,%2,%3},{%4,%5,%6,%7},{%8,%9},{%0,%1,%2,%3};\n"
        : "+f"(c[0]), "+f"(c[1]), "+f"(c[2]), "+f"(c[3])
        : "r"(a[0]), "r"(a[1]), "r"(a[2]), "r"(a[3]), "r"(b0), "r"(b1));
}

// ---------------- Z: zero stat accumulators ----------------
__global__ void kZero() {
    int t = threadIdx.x;  // 512
    if (t < 96) g_simStats[t] = 0.f;
    g_outStats[t & 511] = 0.f;
    g_qkvStats[t & 511] = 0.f;
}

// ---------------- A: qkv GEMM, 8x8 thread tiles + fused BN stats ----------------
// grid (4, 128): bx = ot*2 + jh. 128 thr, smem ~100KB -> 2 CTAs/SM.
__global__ __launch_bounds__(128) void kA(const float* __restrict__ x,
                                          const float* __restrict__ W) {
    extern __shared__ float sm[];
    float* sa = sm;              // [128 k][132]  W^T tile (k-major)
    float* sb = sm + 16896;      // [128 k][68]   x tile (j-half)
    const int ot = blockIdx.x >> 1, jh = blockIdx.x & 1, bh = blockIdx.y;
    const int b0 = bh >> 6, h = bh & 63;
    const int t = threadIdx.x;

    for (int e = 0; e < 128; e++) {
        int idx = e * 128 + t;
        int r = idx >> 7, c = idx & 127;
        sa[c * 132 + r] = W[(ot * 128 + r) * 128 + c];
    }
    for (int e = 0; e < 64; e++) {
        int idx = e * 128 + t;
        int c = idx >> 6, l0 = idx & 63;
        sb[c * 68 + l0] = x[((b0 * 128 + c) * 64 + h) * 128 + jh * 64 + l0];
    }
    __syncthreads();

    const int ty = t >> 3, tx = t & 7;
    const int i0 = ty * 8, j0 = tx * 8;
    float acc[8][8];
#pragma unroll
    for (int u = 0; u < 8; u++)
#pragma unroll
        for (int v = 0; v < 8; v++) acc[u][v] = 0.f;

#pragma unroll 2
    for (int k = 0; k < 128; k++) {
        float4 A0 = *(const float4*)(sa + k * 132 + i0);
        float4 A1 = *(const float4*)(sa + k * 132 + i0 + 4);
        float4 B0 = *(const float4*)(sb + k * 68 + j0);
        float4 B1 = *(const float4*)(sb + k * 68 + j0 + 4);
        float a[8] = {A0.x, A0.y, A0.z, A0.w, A1.x, A1.y, A1.z, A1.w};
        float b[8] = {B0.x, B0.y, B0.z, B0.w, B1.x, B1.y, B1.z, B1.w};
#pragma unroll
        for (int u = 0; u < 8; u++)
#pragma unroll
            for (int v = 0; v < 8; v++) acc[u][v] += a[u] * b[v];
    }

    float* dst = g_qkv + (size_t)bh * 32768 + (size_t)(ot * 128) * 128 + jh * 64;
#pragma unroll
    for (int u = 0; u < 8; u++) {
        *(float4*)(dst + (i0 + u) * 128 + j0)     = make_float4(acc[u][0], acc[u][1], acc[u][2], acc[u][3]);
        *(float4*)(dst + (i0 + u) * 128 + j0 + 4) = make_float4(acc[u][4], acc[u][5], acc[u][6], acc[u][7]);
        float s = 0.f, s2 = 0.f;
#pragma unroll
        for (int v = 0; v < 8; v++) { s += acc[u][v]; s2 += acc[u][v] * acc[u][v]; }
        s = txSum(s);
        s2 = txSum(s2);
        if (tx == 0) {
            int ch = ot * 128 + i0 + u;
            atomicAdd(&g_qkvStats[ch * 2], s);
            atomicAdd(&g_qkvStats[ch * 2 + 1], s2);
        }
    }
}

// ---------------- B': finalize qkv BN ----------------
__global__ void kBf(const float* __restrict__ gamma, const float* __restrict__ beta) {
    int o = threadIdx.x;  // 256
    float S = g_qkvStats[o * 2], S2 = g_qkvStats[o * 2 + 1];
    float mean = S * (1.f / 16384.f);
    float var  = S2 * (1.f / 16384.f) - mean * mean;
    float sc = gamma[o] * rsqrtf(var + EPSF);
    g_scaleQ[o] = sc;
    g_shiftQ[o] = beta[o] - mean * sc;
}

// ---------------- C: shuffle build + 16-warp TC qk + sim stats ----------------
// grid (16, 128), 512 thr
__global__ __launch_bounds__(512) void kC(const float* __restrict__ relemb) {
    extern __shared__ float sm[];
    float* sreq = sm;            // [255][4]
    float* srek = sm + 1024;
    float* sq4  = sm + 2048;     // [128][4]
    float* sk4  = sm + 2560;
    float* sqe  = sm + 3072;     // [128][136]
    float* ske  = sm + 20480;    // [128][136]
    const int g = blockIdx.x, bh = blockIdx.y, t = threadIdx.x;
    const int lane = t & 31, w = t >> 5;

    for (int n = t; n < 1020; n += 512) {
        int c = n & 3, d = n >> 2;
        sreq[n] = relemb[c * 255 + d];
        srek[n] = relemb[(4 + c) * 255 + d];
    }
    for (int n = t; n < 1024; n += 512) {
        int c8 = n >> 7, m = n & 127;
        int o = g * 16 + c8;
        float v = g_qkv[(size_t)bh * 32768 + o * 128 + m] * g_scaleQ[o] + g_shiftQ[o];
        if (c8 < 4) sq4[m * 4 + c8] = v; else sk4[m * 4 + c8 - 4] = v;
    }
    __syncthreads();

    // shuffle-register build: warp = (m-range mw, i-block ib); lane owns i = ib+lane.
    // rel window slides with m via shfl_up; lane 0 loads the fresh entry.
    float sQE = 0.f, sQE2 = 0.f, sKE = 0.f, sKE2 = 0.f;
    {
        const int ib = (w & 3) * 32;
        const int mw = (w >> 2) * 32;
        const int i = ib + lane;
        int d0 = mw - i + 127;
        float4 rq = *(const float4*)(sreq + 4 * d0);
        float4 rk = *(const float4*)(srek + 4 * d0);
#pragma unroll 4
        for (int s = 0; s < 32; s++) {
            int m = mw + s;
            if (s > 0) {
                rq.x = __shfl_up_sync(0xffffffffu, rq.x, 1);
                rq.y = __shfl_up_sync(0xffffffffu, rq.y, 1);
                rq.z = __shfl_up_sync(0xffffffffu, rq.z, 1);
                rq.w = __shfl_up_sync(0xffffffffu, rq.w, 1);
                rk.x = __shfl_up_sync(0xffffffffu, rk.x, 1);
                rk.y = __shfl_up_sync(0xffffffffu, rk.y, 1);
                rk.z = __shfl_up_sync(0xffffffffu, rk.z, 1);
                rk.w = __shfl_up_sync(0xffffffffu, rk.w, 1);
                if (lane == 0) {
                    rq = *(const float4*)(sreq + 4 * (m - ib + 127));
                    rk = *(const float4*)(srek + 4 * (m - ib + 127));
                }
            }
            float4 q4 = *(const float4*)(sq4 + 4 * m);   // broadcast
            float4 k4 = *(const float4*)(sk4 + 4 * m);   // broadcast
            float qe = q4.x * rq.x + q4.y * rq.y + q4.z * rq.z + q4.w * rq.w;
            float ke = k4.x * rk.x + k4.y * rk.y + k4.z * rk.z + k4.w * rk.w;
            sQE += qe; sQE2 += qe * qe; sKE += ke; sKE2 += ke * ke;
            sqe[m * 136 + i] = __uint_as_float(tf32r(qe));
            ske[m * 136 + i] = __uint_as_float(tf32r(ke));
        }
    }
    __syncthreads();

    // qk = qe^T * ke. 16 warps, tile 32(i) x 32(j)
    const int i0w = (w >> 2) * 32, j0w = (w & 3) * 32;
    const int rw = lane >> 2, cl = lane & 3;
    float c[2][4][4];
#pragma unroll
    for (int ii = 0; ii < 2; ii++)
#pragma unroll
        for (int jj = 0; jj < 4; jj++)
#pragma unroll
            for (int u = 0; u < 4; u++) c[ii][jj][u] = 0.f;

    for (int kc = 0; kc < 16; kc++) {
        const int k0 = kc * 8;
        uint32_t a[2][4];
#pragma unroll
        for (int ii = 0; ii < 2; ii++) {
            const float* base = sqe + (k0 + cl) * 136 + i0w + ii * 16 + rw;
            a[ii][0] = __float_as_uint(base[0]);
            a[ii][1] = __float_as_uint(base[8]);
            a[ii][2] = __float_as_uint(base[4 * 136]);
            a[ii][3] = __float_as_uint(base[4 * 136 + 8]);
        }
#pragma unroll
        for (int jj = 0; jj < 4; jj++) {
            const float* bb = ske + (k0 + cl) * 136 + j0w + jj * 8 + rw;
            uint32_t b0 = __float_as_uint(bb[0]);
            uint32_t b1 = __float_as_uint(bb[4 * 136]);
            mma8(c[0][jj], a[0], b0, b1);
            mma8(c[1][jj], a[1], b0, b1);
        }
    }

    float sQK = 0.f, sQK2 = 0.f;
#pragma unroll
    for (int ii = 0; ii < 2; ii++)
#pragma unroll
        for (int jj = 0; jj < 4; jj++)
#pragma unroll
            for (int u = 0; u < 4; u++) { float q = c[ii][jj][u]; sQK += q; sQK2 += q * q; }

    sQK = warpSum(sQK); sQK2 = warpSum(sQK2);
    sQE = warpSum(sQE); sQE2 = warpSum(sQE2);
    sKE = warpSum(sKE); sKE2 = warpSum(sKE2);
    float* red = sq4;  // reuse
    if (lane == 0) {
        red[w * 8 + 0] = sQK; red[w * 8 + 1] = sQK2;
        red[w * 8 + 2] = sQE; red[w * 8 + 3] = sQE2;
        red[w * 8 + 4] = sKE; red[w * 8 + 5] = sKE2;
    }
    __syncthreads();
    if (t < 6) {
        float tot = 0.f;
        for (int i = 0; i < 16; i++) tot += red[i * 8 + t];
        int ch = (t < 2) ? g : (t < 4) ? (16 + g) : (32 + g);
        atomicAdd(&g_simStats[ch * 2 + (t & 1)], tot);
    }
}

// ---------------- D: finalize sim BN scales ----------------
__global__ void kD(const float* __restrict__ gamma_sim) {
    int t = threadIdx.x;
    if (t < 48) {
        const float N = 2097152.f;
        float S = g_simStats[t * 2], S2 = g_simStats[t * 2 + 1];
        float mean = S / N;
        float var = S2 / N - mean * mean;
        g_simScale[t] = gamma_sim[t] * rsqrtf(var + EPSF);
    }
}

// ---------------- E: qk MMA (16w) -> sim -> softmax -> am (MMA) / ame (strips) ------
// grid (16, 128), 512 thr
__global__ __launch_bounds__(512) void kE(const float* __restrict__ relemb) {
    extern __shared__ float sm[];
    float* sreq = sm;            // [255][4]
    float* srek = sm + 1024;
    float* srva = sm + 2048;     // v rel ch 0..3 [d][4]
    float* srvb = sm + 3072;     // v rel ch 4..7 [d][4]
    float* sq4  = sm + 4096;     // [128][4]
    float* sk4  = sm + 4608;
    float* sv8  = sm + 5120;     // v all 8 ch [j][8]
    float* sqe  = sm + 6144;     // [128][136] tf32-rounded; aliased by ssim later
    float* ske  = sm + 23552;    // [128][136]; aliased by amePart later
    float* ssim = sqe;           // [128][133]
    float* amePart = ske;        // [8 c][4 strip][128 i]
    const int g = blockIdx.x, bh = blockIdx.y, t = threadIdx.x;
    const int lane = t & 31, w = t >> 5;
    const int rw = lane >> 2, cl = lane & 3;

    for (int n = t; n < 1020; n += 512) {
        int c = n & 3, d = n >> 2;
        sreq[n] = relemb[c * 255 + d];
        srek[n] = relemb[(4 + c) * 255 + d];
        srva[n] = relemb[(8 + c) * 255 + d];
        srvb[n] = relemb[(12 + c) * 255 + d];
    }
    for (int n = t; n < 2048; n += 512) {
        int c8 = n >> 7, m = n & 127;
        int o = g * 16 + c8;
        float v = g_qkv[(size_t)bh * 32768 + o * 128 + m] * g_scaleQ[o] + g_shiftQ[o];
        if (c8 < 4)       sq4[m * 4 + c8] = v;
        else if (c8 < 8)  sk4[m * 4 + c8 - 4] = v;
        else              sv8[m * 8 + c8 - 8] = v;
    }
    __syncthreads();

    for (int e = 0; e < 32; e++) {
        int idx = e * 512 + t;
        int m = idx >> 7, i = idx & 127;
        int d = m - i + 127;
        float4 qv = *(const float4*)(sq4 + 4 * m);
        float4 rq = *(const float4*)(sreq + 4 * d);
        float4 kv = *(const float4*)(sk4 + 4 * m);
        float4 rk = *(const float4*)(srek + 4 * d);
        float qe = qv.x * rq.x + qv.y * rq.y + qv.z * rq.z + qv.w * rq.w;
        float ke = kv.x * rk.x + kv.y * rk.y + kv.z * rk.z + kv.w * rk.w;
        sqe[m * 136 + i] = __uint_as_float(tf32r(qe));
        ske[m * 136 + i] = __uint_as_float(tf32r(ke));
    }
    __syncthreads();

    // qk MMA: 16 warps, 32x32 tiles, + combine into fragments
    const float a1 = g_simScale[g], a2 = g_simScale[16 + g], a3 = g_simScale[32 + g];
    const int i0w = (w >> 2) * 32, j0w = (w & 3) * 32;
    float c[2][4][4];
#pragma unroll
    for (int ii = 0; ii < 2; ii++)
#pragma unroll
        for (int jj = 0; jj < 4; jj++)
#pragma unroll
            for (int u = 0; u < 4; u++) c[ii][jj][u] = 0.f;

    for (int kc = 0; kc < 16; kc++) {
        const int k0 = kc * 8;
        uint32_t a[2][4];
#pragma unroll
        for (int ii = 0; ii < 2; ii++) {
            const float* base = sqe + (k0 + cl) * 136 + i0w + ii * 16 + rw;
            a[ii][0] = __float_as_uint(base[0]);
            a[ii][1] = __float_as_uint(base[8]);
            a[ii][2] = __float_as_uint(base[4 * 136]);
            a[ii][3] = __float_as_uint(base[4 * 136 + 8]);
        }
#pragma unroll
        for (int jj = 0; jj < 4; jj++) {
            const float* bb = ske + (k0 + cl) * 136 + j0w + jj * 8 + rw;
            uint32_t b0 = __float_as_uint(bb[0]);
            uint32_t b1 = __float_as_uint(bb[4 * 136]);
            mma8(c[0][jj], a[0], b0, b1);
            mma8(c[1][jj], a[1], b0, b1);
        }
    }

    // combine: sim = a1*qk + a2*qe + a3*ke at fragment coords
#pragma unroll
    for (int ii = 0; ii < 2; ii++)
#pragma unroll
        for (int jj = 0; jj < 4; jj++) {
            int ir0 = i0w + ii * 16 + rw;
            int jc = j0w + jj * 8 + 2 * cl;
            float2 q0 = *(const float2*)(sqe + ir0 * 136 + jc);
            float2 k0 = *(const float2*)(ske + ir0 * 136 + jc);
            float2 q1 = *(const float2*)(sqe + (ir0 + 8) * 136 + jc);
            float2 k1 = *(const float2*)(ske + (ir0 + 8) * 136 + jc);
            float* cc = c[ii][jj];
            cc[0] = a1 * cc[0] + a2 * q0.x + a3 * k0.x;
            cc[1] = a1 * cc[1] + a2 * q0.y + a3 * k0.y;
            cc[2] = a1 * cc[2] + a2 * q1.x + a3 * k1.x;
            cc[3] = a1 * cc[3] + a2 * q1.y + a3 * k1.y;
        }
    __syncthreads();   // all sqe/ske reads done; safe to overwrite with ssim

#pragma unroll
    for (int ii = 0; ii < 2; ii++)
#pragma unroll
        for (int jj = 0; jj < 4; jj++) {
            int ir0 = i0w + ii * 16 + rw;
            int jc = j0w + jj * 8 + 2 * cl;
            float* cc = c[ii][jj];
            ssim[ir0 * 133 + jc] = cc[0];
            ssim[ir0 * 133 + jc + 1] = cc[1];
            ssim[(ir0 + 8) * 133 + jc] = cc[2];
            ssim[(ir0 + 8) * 133 + jc + 1] = cc[3];
        }
    __syncthreads();

    // softmax over j: 16 warps x 8 rows
    for (int r = 0; r < 8; r++) {
        int i = w * 8 + r;
        float* row = ssim + i * 133;
        float x0 = row[lane], x1 = row[lane + 32], x2 = row[lane + 64], x3 = row[lane + 96];
        float mx = fmaxf(fmaxf(x0, x1), fmaxf(x2, x3));
#pragma unroll
        for (int o = 16; o > 0; o >>= 1) mx = fmaxf(mx, __shfl_xor_sync(0xffffffffu, mx, o));
        float e0 = __expf(x0 - mx), e1 = __expf(x1 - mx);
        float e2 = __expf(x2 - mx), e3 = __expf(x3 - mx);
        float s = warpSum(e0 + e1 + e2 + e3);
        float inv = 1.f / s;
        row[lane] = e0 * inv; row[lane + 32] = e1 * inv;
        row[lane + 64] = e2 * inv; row[lane + 96] = e3 * inv;
    }
    __syncthreads();

    // ame strips: thread owns (i, strip of 32 j), all 8 channels -> partials to smem
    {
        const int i = t & 127, s = t >> 7;
        float accE[8] = {0.f, 0.f, 0.f, 0.f, 0.f, 0.f, 0.f, 0.f};
        const int jb = s * 32;
        for (int jj = 0; jj < 32; jj++) {
            int j = jb + jj;
            float p = ssim[i * 133 + j];
            int d = i - j + 127;
            float4 ra = *(const float4*)(srva + 4 * d);
            float4 rb = *(const float4*)(srvb + 4 * d);
            accE[0] += p * ra.x; accE[1] += p * ra.y; accE[2] += p * ra.z; accE[3] += p * ra.w;
            accE[4] += p * rb.x; accE[5] += p * rb.y; accE[6] += p * rb.z; accE[7] += p * rb.w;
        }
        __syncthreads();   // ske reads fully done earlier; amePart aliases ske
#pragma unroll
        for (int ch = 0; ch < 8; ch++)
            amePart[ch * 512 + s * 128 + i] = accE[ch];
    }
    __syncthreads();

    float* dst = g_outraw + (size_t)bh * 32768;
    if (w < 8) {
        // am via tf32 MMA: A = P (ssim), B = v (sv8). m-tile per warp: i0 = w*16
        const int i0 = w * 16;
        float ca[4] = {0.f, 0.f, 0.f, 0.f};
        for (int kc = 0; kc < 16; kc++) {
            const int k0 = kc * 8;
            const float* pr0 = ssim + (i0 + rw) * 133 + k0 + cl;
            const float* pr1 = pr0 + 8 * 133;
            uint32_t a[4];
            a[0] = tf32r(pr0[0]);
            a[1] = tf32r(pr1[0]);
            a[2] = tf32r(pr0[4]);
            a[3] = tf32r(pr1[4]);
            uint32_t b0 = tf32r(sv8[(k0 + cl) * 8 + rw]);
            uint32_t b1 = tf32r(sv8[(k0 + cl + 4) * 8 + rw]);
            mma8(ca, a, b0, b1);
        }
        const int i1 = i0 + rw, i2 = i0 + rw + 8;
        const int ch0 = 2 * cl, ch1 = 2 * cl + 1;
        const int o0 = g * 16 + 2 * ch0, o1 = g * 16 + 2 * ch1;
        dst[o0 * 128 + i1] = ca[0];
        dst[o1 * 128 + i1] = ca[1];
        dst[o0 * 128 + i2] = ca[2];
        dst[o1 * 128 + i2] = ca[3];
        // am stats (per-warp partial over 16 rows -> atomics)
        float s0 = ca[0] + ca[2], s02 = ca[0] * ca[0] + ca[2] * ca[2];
        float s1 = ca[1] + ca[3], s12 = ca[1] * ca[1] + ca[3] * ca[3];
        s0 = rwSum(s0); s02 = rwSum(s02); s1 = rwSum(s1); s12 = rwSum(s12);
        if (rw == 0) {
            atomicAdd(&g_outStats[o0 * 2], s0);
            atomicAdd(&g_outStats[o0 * 2 + 1], s02);
            atomicAdd(&g_outStats[o1 * 2], s1);
            atomicAdd(&g_outStats[o1 * 2 + 1], s12);
        }
    } else {
        // ame reduce: warp r handles channel c=r; lane covers 4 consecutive i
        const int ch = w - 8;
        const int iB = lane * 4;
        float4 v0 = *(const float4*)(amePart + ch * 512 + 0 * 128 + iB);
        float4 v1 = *(const float4*)(amePart + ch * 512 + 1 * 128 + iB);
        float4 v2 = *(const float4*)(amePart + ch * 512 + 2 * 128 + iB);
        float4 v3 = *(const float4*)(amePart + ch * 512 + 3 * 128 + iB);
        float4 r4 = make_float4(v0.x + v1.x + v2.x + v3.x,
                                v0.y + v1.y + v2.y + v3.y,
                                v0.z + v1.z + v2.z + v3.z,
                                v0.w + v1.w + v2.w + v3.w);
        const int o = g * 16 + 2 * ch + 1;
        *(float4*)(dst + o * 128 + iB) = r4;
        float sE = r4.x + r4.y + r4.z + r4.w;
        float sE2 = r4.x * r4.x + r4.y * r4.y + r4.z * r4.z + r4.w * r4.w;
        sE = warpSum(sE); sE2 = warpSum(sE2);
        if (lane == 0) {
            atomicAdd(&g_outStats[o * 2], sE);
            atomicAdd(&g_outStats[o * 2 + 1], sE2);
        }
    }
}

// ---------------- F: finalize out BN params ----------------
__global__ void kF(const float* __restrict__ gamma_out, const float* __restrict__ beta_out) {
    int o = threadIdx.x;  // 256
    const float N = 16384.f;
    float S = g_outStats[o * 2], S2 = g_outStats[o * 2 + 1];
    float mean = S / N;
    float var = S2 / N - mean * mean;
    float sc = gamma_out[o] * rsqrtf(var + EPSF);
    g_outScale[o] = sc;
    g_outShift[o] = beta_out[o] - mean * sc;
}

// ---------------- G: y = bn(out)[2oc] + bn(out)[2oc+1] ----------------
__global__ __launch_bounds__(256) void kG(float* __restrict__ y) {
    int idx = blockIdx.x * 256 + threadIdx.x;
    int wpos = idx & 127;
    int h = (idx >> 7) & 63;
    int oc = (idx >> 13) & 127;
    int b0 = idx >> 20;
    int bh = b0 * 64 + h;
    int o = oc * 2;
    float v0 = g_outraw[(size_t)bh * 32768 + o * 128 + wpos];
    float v1 = g_outraw[(size_t)bh * 32768 + (o + 1) * 128 + wpos];
    y[idx] = (v0 * g_outScale[o] + g_outShift[o]) + (v1 * g_outScale[o + 1] + g_outShift[o + 1]);
}

// ---------------- launch ----------------
extern "C" void kernel_launch(void* const* d_in, const int* in_sizes, int n_in,
                              void* d_out, int out_size) {
    const float* x  = (const float*)d_in[0];
    const float* W  = (const float*)d_in[1];
    const float* gq = (const float*)d_in[2];
    const float* bq = (const float*)d_in[3];
    const float* re = (const float*)d_in[4];
    const float* gs = (const float*)d_in[5];
    // beta_sim (d_in[6]) cancels inside softmax — unused
    const float* go = (const float*)d_in[7];
    const float* bo = (const float*)d_in[8];
    float* y = (float*)d_out;

    const int SMEM_A = (16896 + 128 * 68) * 4;       // 102400
    const int SMEM_C = (20480 + 17408) * 4;          // 151552
    const int SMEM_E = (23552 + 17408) * 4;          // 163840

    cudaFuncSetAttribute(kA, cudaFuncAttributeMaxDynamicSharedMemorySize, SMEM_A);
    cudaFuncSetAttribute(kC, cudaFuncAttributeMaxDynamicSharedMemorySize, SMEM_C);
    cudaFuncSetAttribute(kE, cudaFuncAttributeMaxDynamicSharedMemorySize, SMEM_E);

    kZero<<<1, 512>>>();
    kA<<<dim3(4, 128), 128, SMEM_A>>>(x, W);
    kBf<<<1, 256>>>(gq, bq);
    kC<<<dim3(16, 128), 512, SMEM_C>>>(re);
    kD<<<1, 64>>>(gs);
    kE<<<dim3(16, 128), 512, SMEM_E>>>(re);
    kF<<<1, 256>>>(go, bo);
    kG<<<8192, 256>>>(y);
}

// round 12
// speedup vs baseline: 1.1008x; 1.1008x over previous
#include <cuda_runtime.h>
#include <cuda_bf16.h>
#include <math.h>
#include <stdint.h>

#define EPSF 1e-5f

// ---------------- scratch (device globals) ----------------
__device__ float g_qkv[4194304];      // [128 bh][256 o][128 l]
__device__ float g_outraw[4194304];   // [128 bh][256 o][128 i]
__device__ float g_qkvStats[512];     // [256 ch][sum,sumsq]
__device__ float g_simStats[96];
__device__ float g_outStats[512];
__device__ float g_scaleQ[256];
__device__ float g_shiftQ[256];
__device__ float g_simScale[48];
__device__ float g_outScale[256];
__device__ float g_outShift[256];

__device__ __forceinline__ float warpSum(float v) {
#pragma unroll
    for (int o = 16; o > 0; o >>= 1) v += __shfl_xor_sync(0xffffffffu, v, o);
    return v;
}

// sum across the 8 lanes differing in bits 0..2 (tx groups in kA)
__device__ __forceinline__ float txSum(float v) {
    v += __shfl_xor_sync(0xffffffffu, v, 1);
    v += __shfl_xor_sync(0xffffffffu, v, 2);
    v += __shfl_xor_sync(0xffffffffu, v, 4);
    return v;
}

// reduce across lanes that differ only in bits 2..4 (rw groups, cl fixed)
__device__ __forceinline__ float rwSum(float v) {
    v += __shfl_xor_sync(0xffffffffu, v, 4);
    v += __shfl_xor_sync(0xffffffffu, v, 8);
    v += __shfl_xor_sync(0xffffffffu, v, 16);
    return v;
}

__device__ __forceinline__ uint32_t tf32r(float x) {
    uint32_t u;
    asm("cvt.rna.tf32.f32 %0, %1;" : "=r"(u) : "f"(x));
    return u;
}

__device__ __forceinline__ uint32_t packbf(float a, float b) {
    __nv_bfloat162 h = __floats2bfloat162_rn(a, b);
    return *(uint32_t*)&h;
}

__device__ __forceinline__ void mma8(float* c, const uint32_t* a, uint32_t b0, uint32_t b1) {
    asm volatile(
        "mma.sync.aligned.m16n8k8.row.col.f32.tf32.tf32.f32 "
        "{%0,%1,%2,%3},{%4,%5,%6,%7},{%8,%9},{%0,%1,%2,%3};\n"
        : "+f"(c[0]), "+f"(c[1]), "+f"(c[2]), "+f"(c[3])
        : "r"(a[0]), "r"(a[1]), "r"(a[2]), "r"(a[3]), "r"(b0), "r"(b1));
}

__device__ __forceinline__ void mma16(float* c, const uint32_t* a, uint32_t b0, uint32_t b1) {
    asm volatile(
        "mma.sync.aligned.m16n8k16.row.col.f32.bf16.bf16.f32 "
        "{%0,%1,%2,%3},{%4,%5,%6,%7},{%8,%9},{%0,%1,%2,%3};\n"
        : "+f"(c[0]), "+f"(c[1]), "+f"(c[2]), "+f"(c[3])
        : "r"(a[0]), "r"(a[1]), "r"(a[2]), "r"(a[3]), "r"(b0), "r"(b1));
}

// ---------------- Z: zero stat accumulators ----------------
__global__ void kZero() {
    int t = threadIdx.x;  // 512
    if (t < 96) g_simStats[t] = 0.f;
    g_outStats[t & 511] = 0.f;
    g_qkvStats[t & 511] = 0.f;
}

// ---------------- A: qkv GEMM, 8x8 thread tiles + fused BN stats ----------------
// grid (4, 128): bx = ot*2 + jh. 128 thr, smem ~100KB -> 2 CTAs/SM.
__global__ __launch_bounds__(128) void kA(const float* __restrict__ x,
                                          const float* __restrict__ W) {
    extern __shared__ float sm[];
    float* sa = sm;              // [128 k][132]  W^T tile (k-major)
    float* sb = sm + 16896;      // [128 k][68]   x tile (j-half)
    const int ot = blockIdx.x >> 1, jh = blockIdx.x & 1, bh = blockIdx.y;
    const int b0 = bh >> 6, h = bh & 63;
    const int t = threadIdx.x;

    for (int e = 0; e < 128; e++) {
        int idx = e * 128 + t;
        int r = idx >> 7, c = idx & 127;
        sa[c * 132 + r] = W[(ot * 128 + r) * 128 + c];
    }
    for (int e = 0; e < 64; e++) {
        int idx = e * 128 + t;
        int c = idx >> 6, l0 = idx & 63;
        sb[c * 68 + l0] = x[((b0 * 128 + c) * 64 + h) * 128 + jh * 64 + l0];
    }
    __syncthreads();

    const int ty = t >> 3, tx = t & 7;
    const int i0 = ty * 8, j0 = tx * 8;
    float acc[8][8];
#pragma unroll
    for (int u = 0; u < 8; u++)
#pragma unroll
        for (int v = 0; v < 8; v++) acc[u][v] = 0.f;

#pragma unroll 2
    for (int k = 0; k < 128; k++) {
        float4 A0 = *(const float4*)(sa + k * 132 + i0);
        float4 A1 = *(const float4*)(sa + k * 132 + i0 + 4);
        float4 B0 = *(const float4*)(sb + k * 68 + j0);
        float4 B1 = *(const float4*)(sb + k * 68 + j0 + 4);
        float a[8] = {A0.x, A0.y, A0.z, A0.w, A1.x, A1.y, A1.z, A1.w};
        float b[8] = {B0.x, B0.y, B0.z, B0.w, B1.x, B1.y, B1.z, B1.w};
#pragma unroll
        for (int u = 0; u < 8; u++)
#pragma unroll
            for (int v = 0; v < 8; v++) acc[u][v] += a[u] * b[v];
    }

    float* dst = g_qkv + (size_t)bh * 32768 + (size_t)(ot * 128) * 128 + jh * 64;
#pragma unroll
    for (int u = 0; u < 8; u++) {
        *(float4*)(dst + (i0 + u) * 128 + j0)     = make_float4(acc[u][0], acc[u][1], acc[u][2], acc[u][3]);
        *(float4*)(dst + (i0 + u) * 128 + j0 + 4) = make_float4(acc[u][4], acc[u][5], acc[u][6], acc[u][7]);
        float s = 0.f, s2 = 0.f;
#pragma unroll
        for (int v = 0; v < 8; v++) { s += acc[u][v]; s2 += acc[u][v] * acc[u][v]; }
        s = txSum(s);
        s2 = txSum(s2);
        if (tx == 0) {
            int ch = ot * 128 + i0 + u;
            atomicAdd(&g_qkvStats[ch * 2], s);
            atomicAdd(&g_qkvStats[ch * 2 + 1], s2);
        }
    }
}

// ---------------- B': finalize qkv BN ----------------
__global__ void kBf(const float* __restrict__ gamma, const float* __restrict__ beta) {
    int o = threadIdx.x;  // 256
    float S = g_qkvStats[o * 2], S2 = g_qkvStats[o * 2 + 1];
    float mean = S * (1.f / 16384.f);
    float var  = S2 * (1.f / 16384.f) - mean * mean;
    float sc = gamma[o] * rsqrtf(var + EPSF);
    g_scaleQ[o] = sc;
    g_shiftQ[o] = beta[o] - mean * sc;
}

// ---------------- C: bf16 build + bf16 m16n8k16 qk + sim stats ----------------
// Stats-only qk: bf16 element errors average out over 2M samples (bias ~ eps^2).
// smem 80KB -> 2 CTAs/SM.
// grid (16, 128), 512 thr
__global__ __launch_bounds__(512, 2) void kC(const float* __restrict__ relemb) {
    extern __shared__ float sm[];
    float* sreq = sm;            // [255][4]
    float* srek = sm + 1024;
    float* sq4  = sm + 2048;     // [128][4]
    float* sk4  = sm + 2560;
    uint32_t* sqe16 = (uint32_t*)(sm + 3072);    // [128 i][68 words], word = (m0,m1) bf16x2
    uint32_t* ske16 = (uint32_t*)(sm + 11776);   // [128 j][68 words]
    const int g = blockIdx.x, bh = blockIdx.y, t = threadIdx.x;
    const int lane = t & 31, w = t >> 5;

    for (int n = t; n < 1020; n += 512) {
        int c = n & 3, d = n >> 2;
        sreq[n] = relemb[c * 255 + d];
        srek[n] = relemb[(4 + c) * 255 + d];
    }
    for (int n = t; n < 1024; n += 512) {
        int c8 = n >> 7, m = n & 127;
        int o = g * 16 + c8;
        float v = g_qkv[(size_t)bh * 32768 + o * 128 + m] * g_scaleQ[o] + g_shiftQ[o];
        if (c8 < 4) sq4[m * 4 + c8] = v; else sk4[m * 4 + c8 - 4] = v;
    }
    __syncthreads();

    // build: thread handles (m-pair mh, i); lanes consecutive i, mh fixed per warp-iter
    float sQE = 0.f, sQE2 = 0.f, sKE = 0.f, sKE2 = 0.f;
    for (int e = 0; e < 16; e++) {
        int idx = e * 512 + t;
        int mh = idx >> 7;        // 0..63
        int i  = idx & 127;
        int m0 = mh * 2;
        float4 qa = *(const float4*)(sq4 + 4 * m0);
        float4 qb = *(const float4*)(sq4 + 4 * m0 + 4);
        float4 ka = *(const float4*)(sk4 + 4 * m0);
        float4 kb = *(const float4*)(sk4 + 4 * m0 + 4);
        int d0 = m0 - i + 127;    // m1 uses d0+1 (max 254, in range)
        float4 rq0 = *(const float4*)(sreq + 4 * d0);
        float4 rq1 = *(const float4*)(sreq + 4 * d0 + 4);
        float4 rk0 = *(const float4*)(srek + 4 * d0);
        float4 rk1 = *(const float4*)(srek + 4 * d0 + 4);
        float qe0 = qa.x * rq0.x + qa.y * rq0.y + qa.z * rq0.z + qa.w * rq0.w;
        float qe1 = qb.x * rq1.x + qb.y * rq1.y + qb.z * rq1.z + qb.w * rq1.w;
        float ke0 = ka.x * rk0.x + ka.y * rk0.y + ka.z * rk0.z + ka.w * rk0.w;
        float ke1 = kb.x * rk1.x + kb.y * rk1.y + kb.z * rk1.z + kb.w * rk1.w;
        sQE += qe0 + qe1; sQE2 += qe0 * qe0 + qe1 * qe1;
        sKE += ke0 + ke1; sKE2 += ke0 * ke0 + ke1 * ke1;
        sqe16[i * 68 + mh] = packbf(qe0, qe1);
        ske16[i * 68 + mh] = packbf(ke0, ke1);
    }
    __syncthreads();

    // qk = qe^T * ke via bf16 m16n8k16. 16 warps, tile 32(i) x 32(j).
    // A[i][m] = sqe16 row i; B[m][j] = ske16 row j (col-major n8k16).
    const int i0w = (w >> 2) * 32, j0w = (w & 3) * 32;
    const int rw = lane >> 2, cl = lane & 3;
    float c[2][4][4];
#pragma unroll
    for (int ii = 0; ii < 2; ii++)
#pragma unroll
        for (int jj = 0; jj < 4; jj++)
#pragma unroll
            for (int u = 0; u < 4; u++) c[ii][jj][u] = 0.f;

    for (int kc = 0; kc < 8; kc++) {
        const int kw = kc * 8;    // word offset (16 bf16 = 8 words per step)
        uint32_t a[2][4];
#pragma unroll
        for (int ii = 0; ii < 2; ii++) {
            const uint32_t* base = sqe16 + (i0w + ii * 16 + rw) * 68 + kw + cl;
            a[ii][0] = base[0];
            a[ii][1] = base[8 * 68];
            a[ii][2] = base[4];
            a[ii][3] = base[8 * 68 + 4];
        }
#pragma unroll
        for (int jj = 0; jj < 4; jj++) {
            const uint32_t* bb = ske16 + (j0w + jj * 8 + rw) * 68 + kw + cl;
            uint32_t b0 = bb[0];
            uint32_t b1 = bb[4];
            mma16(c[0][jj], a[0], b0, b1);
            mma16(c[1][jj], a[1], b0, b1);
        }
    }

    float sQK = 0.f, sQK2 = 0.f;
#pragma unroll
    for (int ii = 0; ii < 2; ii++)
#pragma unroll
        for (int jj = 0; jj < 4; jj++)
#pragma unroll
            for (int u = 0; u < 4; u++) { float q = c[ii][jj][u]; sQK += q; sQK2 += q * q; }

    sQK = warpSum(sQK); sQK2 = warpSum(sQK2);
    sQE = warpSum(sQE); sQE2 = warpSum(sQE2);
    sKE = warpSum(sKE); sKE2 = warpSum(sKE2);
    float* red = sq4;  // reuse
    if (lane == 0) {
        red[w * 8 + 0] = sQK; red[w * 8 + 1] = sQK2;
        red[w * 8 + 2] = sQE; red[w * 8 + 3] = sQE2;
        red[w * 8 + 4] = sKE; red[w * 8 + 5] = sKE2;
    }
    __syncthreads();
    if (t < 6) {
        float tot = 0.f;
        for (int i = 0; i < 16; i++) tot += red[i * 8 + t];
        int ch = (t < 2) ? g : (t < 4) ? (16 + g) : (32 + g);
        atomicAdd(&g_simStats[ch * 2 + (t & 1)], tot);
    }
}

// ---------------- D: finalize sim BN scales ----------------
__global__ void kD(const float* __restrict__ gamma_sim) {
    int t = threadIdx.x;
    if (t < 48) {
        const float N = 2097152.f;
        float S = g_simStats[t * 2], S2 = g_simStats[t * 2 + 1];
        float mean = S / N;
        float var = S2 / N - mean * mean;
        g_simScale[t] = gamma_sim[t] * rsqrtf(var + EPSF);
    }
}

// ---------------- E: qk MMA (16w tf32) -> sim -> softmax -> am (MMA) / ame (strips) --
// grid (16, 128), 512 thr
__global__ __launch_bounds__(512) void kE(const float* __restrict__ relemb) {
    extern __shared__ float sm[];
    float* sreq = sm;            // [255][4]
    float* srek = sm + 1024;
    float* srva = sm + 2048;     // v rel ch 0..3 [d][4]
    float* srvb = sm + 3072;     // v rel ch 4..7 [d][4]
    float* sq4  = sm + 4096;     // [128][4]
    float* sk4  = sm + 4608;
    float* sv8  = sm + 5120;     // v all 8 ch [j][8]
    float* sqe  = sm + 6144;     // [128][136] tf32-rounded; aliased by ssim later
    float* ske  = sm + 23552;    // [128][136]; aliased by amePart later
    float* ssim = sqe;           // [128][133]
    float* amePart = ske;        // [8 c][4 strip][128 i]
    const int g = blockIdx.x, bh = blockIdx.y, t = threadIdx.x;
    const int lane = t & 31, w = t >> 5;
    const int rw = lane >> 2, cl = lane & 3;

    for (int n = t; n < 1020; n += 512) {
        int c = n & 3, d = n >> 2;
        sreq[n] = relemb[c * 255 + d];
        srek[n] = relemb[(4 + c) * 255 + d];
        srva[n] = relemb[(8 + c) * 255 + d];
        srvb[n] = relemb[(12 + c) * 255 + d];
    }
    for (int n = t; n < 2048; n += 512) {
        int c8 = n >> 7, m = n & 127;
        int o = g * 16 + c8;
        float v = g_qkv[(size_t)bh * 32768 + o * 128 + m] * g_scaleQ[o] + g_shiftQ[o];
        if (c8 < 4)       sq4[m * 4 + c8] = v;
        else if (c8 < 8)  sk4[m * 4 + c8 - 4] = v;
        else              sv8[m * 8 + c8 - 8] = v;
    }
    __syncthreads();

    for (int e = 0; e < 32; e++) {
        int idx = e * 512 + t;
        int m = idx >> 7, i = idx & 127;
        int d = m - i + 127;
        float4 qv = *(const float4*)(sq4 + 4 * m);
        float4 rq = *(const float4*)(sreq + 4 * d);
        float4 kv = *(const float4*)(sk4 + 4 * m);
        float4 rk = *(const float4*)(srek + 4 * d);
        float qe = qv.x * rq.x + qv.y * rq.y + qv.z * rq.z + qv.w * rq.w;
        float ke = kv.x * rk.x + kv.y * rk.y + kv.z * rk.z + kv.w * rk.w;
        sqe[m * 136 + i] = __uint_as_float(tf32r(qe));
        ske[m * 136 + i] = __uint_as_float(tf32r(ke));
    }
    __syncthreads();

    // qk MMA: 16 warps, 32x32 tiles, + combine into fragments
    const float a1 = g_simScale[g], a2 = g_simScale[16 + g], a3 = g_simScale[32 + g];
    const int i0w = (w >> 2) * 32, j0w = (w & 3) * 32;
    float c[2][4][4];
#pragma unroll
    for (int ii = 0; ii < 2; ii++)
#pragma unroll
        for (int jj = 0; jj < 4; jj++)
#pragma unroll
            for (int u = 0; u < 4; u++) c[ii][jj][u] = 0.f;

    for (int kc = 0; kc < 16; kc++) {
        const int k0 = kc * 8;
        uint32_t a[2][4];
#pragma unroll
        for (int ii = 0; ii < 2; ii++) {
            const float* base = sqe + (k0 + cl) * 136 + i0w + ii * 16 + rw;
            a[ii][0] = __float_as_uint(base[0]);
            a[ii][1] = __float_as_uint(base[8]);
            a[ii][2] = __float_as_uint(base[4 * 136]);
            a[ii][3] = __float_as_uint(base[4 * 136 + 8]);
        }
#pragma unroll
        for (int jj = 0; jj < 4; jj++) {
            const float* bb = ske + (k0 + cl) * 136 + j0w + jj * 8 + rw;
            uint32_t b0 = __float_as_uint(bb[0]);
            uint32_t b1 = __float_as_uint(bb[4 * 136]);
            mma8(c[0][jj], a[0], b0, b1);
            mma8(c[1][jj], a[1], b0, b1);
        }
    }

    // combine: sim = a1*qk + a2*qe + a3*ke at fragment coords
#pragma unroll
    for (int ii = 0; ii < 2; ii++)
#pragma unroll
        for (int jj = 0; jj < 4; jj++) {
            int ir0 = i0w + ii * 16 + rw;
            int jc = j0w + jj * 8 + 2 * cl;
            float2 q0 = *(const float2*)(sqe + ir0 * 136 + jc);
            float2 k0 = *(const float2*)(ske + ir0 * 136 + jc);
            float2 q1 = *(const float2*)(sqe + (ir0 + 8) * 136 + jc);
            float2 k1 = *(const float2*)(ske + (ir0 + 8) * 136 + jc);
            float* cc = c[ii][jj];
            cc[0] = a1 * cc[0] + a2 * q0.x + a3 * k0.x;
            cc[1] = a1 * cc[1] + a2 * q0.y + a3 * k0.y;
            cc[2] = a1 * cc[2] + a2 * q1.x + a3 * k1.x;
            cc[3] = a1 * cc[3] + a2 * q1.y + a3 * k1.y;
        }
    __syncthreads();   // all sqe/ske reads done; safe to overwrite with ssim

#pragma unroll
    for (int ii = 0; ii < 2; ii++)
#pragma unroll
        for (int jj = 0; jj < 4; jj++) {
            int ir0 = i0w + ii * 16 + rw;
            int jc = j0w + jj * 8 + 2 * cl;
            float* cc = c[ii][jj];
            ssim[ir0 * 133 + jc] = cc[0];
            ssim[ir0 * 133 + jc + 1] = cc[1];
            ssim[(ir0 + 8) * 133 + jc] = cc[2];
            ssim[(ir0 + 8) * 133 + jc + 1] = cc[3];
        }
    __syncthreads();

    // softmax over j: 16 warps x 8 rows
    for (int r = 0; r < 8; r++) {
        int i = w * 8 + r;
        float* row = ssim + i * 133;
        float x0 = row[lane], x1 = row[lane + 32], x2 = row[lane + 64], x3 = row[lane + 96];
        float mx = fmaxf(fmaxf(x0, x1), fmaxf(x2, x3));
#pragma unroll
        for (int o = 16; o > 0; o >>= 1) mx = fmaxf(mx, __shfl_xor_sync(0xffffffffu, mx, o));
        float e0 = __expf(x0 - mx), e1 = __expf(x1 - mx);
        float e2 = __expf(x2 - mx), e3 = __expf(x3 - mx);
        float s = warpSum(e0 + e1 + e2 + e3);
        float inv = 1.f / s;
        row[lane] = e0 * inv; row[lane + 32] = e1 * inv;
        row[lane + 64] = e2 * inv; row[lane + 96] = e3 * inv;
    }
    __syncthreads();

    // ame strips: thread owns (i, strip of 32 j), all 8 channels -> partials to smem
    {
        const int i = t & 127, s = t >> 7;
        float accE[8] = {0.f, 0.f, 0.f, 0.f, 0.f, 0.f, 0.f, 0.f};
        const int jb = s * 32;
        for (int jj = 0; jj < 32; jj++) {
            int j = jb + jj;
            float p = ssim[i * 133 + j];
            int d = i - j + 127;
            float4 ra = *(const float4*)(srva + 4 * d);
            float4 rb = *(const float4*)(srvb + 4 * d);
            accE[0] += p * ra.x; accE[1] += p * ra.y; accE[2] += p * ra.z; accE[3] += p * ra.w;
            accE[4] += p * rb.x; accE[5] += p * rb.y; accE[6] += p * rb.z; accE[7] += p * rb.w;
        }
        __syncthreads();   // ske reads fully done earlier; amePart aliases ske
#pragma unroll
        for (int ch = 0; ch < 8; ch++)
            amePart[ch * 512 + s * 128 + i] = accE[ch];
    }
    __syncthreads();

    float* dst = g_outraw + (size_t)bh * 32768;
    if (w < 8) {
        // am via tf32 MMA: A = P (ssim), B = v (sv8). m-tile per warp: i0 = w*16
        const int i0 = w * 16;
        float ca[4] = {0.f, 0.f, 0.f, 0.f};
        for (int kc = 0; kc < 16; kc++) {
            const int k0 = kc * 8;
            const float* pr0 = ssim + (i0 + rw) * 133 + k0 + cl;
            const float* pr1 = pr0 + 8 * 133;
            uint32_t a[4];
            a[0] = tf32r(pr0[0]);
            a[1] = tf32r(pr1[0]);
            a[2] = tf32r(pr0[4]);
            a[3] = tf32r(pr1[4]);
            uint32_t b0 = tf32r(sv8[(k0 + cl) * 8 + rw]);
            uint32_t b1 = tf32r(sv8[(k0 + cl + 4) * 8 + rw]);
            mma8(ca, a, b0, b1);
        }
        const int i1 = i0 + rw, i2 = i0 + rw + 8;
        const int ch0 = 2 * cl, ch1 = 2 * cl + 1;
        const int o0 = g * 16 + 2 * ch0, o1 = g * 16 + 2 * ch1;
        dst[o0 * 128 + i1] = ca[0];
        dst[o1 * 128 + i1] = ca[1];
        dst[o0 * 128 + i2] = ca[2];
        dst[o1 * 128 + i2] = ca[3];
        // am stats (per-warp partial over 16 rows -> atomics)
        float s0 = ca[0] + ca[2], s02 = ca[0] * ca[0] + ca[2] * ca[2];
        float s1 = ca[1] + ca[3], s12 = ca[1] * ca[1] + ca[3] * ca[3];
        s0 = rwSum(s0); s02 = rwSum(s02); s1 = rwSum(s1); s12 = rwSum(s12);
        if (rw == 0) {
            atomicAdd(&g_outStats[o0 * 2], s0);
            atomicAdd(&g_outStats[o0 * 2 + 1], s02);
            atomicAdd(&g_outStats[o1 * 2], s1);
            atomicAdd(&g_outStats[o1 * 2 + 1], s12);
        }
    } else {
        // ame reduce: warp r handles channel c=r; lane covers 4 consecutive i
        const int ch = w - 8;
        const int iB = lane * 4;
        float4 v0 = *(const float4*)(amePart + ch * 512 + 0 * 128 + iB);
        float4 v1 = *(const float4*)(amePart + ch * 512 + 1 * 128 + iB);
        float4 v2 = *(const float4*)(amePart + ch * 512 + 2 * 128 + iB);
        float4 v3 = *(const float4*)(amePart + ch * 512 + 3 * 128 + iB);
        float4 r4 = make_float4(v0.x + v1.x + v2.x + v3.x,
                                v0.y + v1.y + v2.y + v3.y,
                                v0.z + v1.z + v2.z + v3.z,
                                v0.w + v1.w + v2.w + v3.w);
        const int o = g * 16 + 2 * ch + 1;
        *(float4*)(dst + o * 128 + iB) = r4;
        float sE = r4.x + r4.y + r4.z + r4.w;
        float sE2 = r4.x * r4.x + r4.y * r4.y + r4.z * r4.z + r4.w * r4.w;
        sE = warpSum(sE); sE2 = warpSum(sE2);
        if (lane == 0) {
            atomicAdd(&g_outStats[o * 2], sE);
            atomicAdd(&g_outStats[o * 2 + 1], sE2);
        }
    }
}

// ---------------- F: finalize out BN params ----------------
__global__ void kF(const float* __restrict__ gamma_out, const float* __restrict__ beta_out) {
    int o = threadIdx.x;  // 256
    const float N = 16384.f;
    float S = g_outStats[o * 2], S2 = g_outStats[o * 2 + 1];
    float mean = S / N;
    float var = S2 / N - mean * mean;
    float sc = gamma_out[o] * rsqrtf(var + EPSF);
    g_outScale[o] = sc;
    g_outShift[o] = beta_out[o] - mean * sc;
}

// ---------------- G: y = bn(out)[2oc] + bn(out)[2oc+1] ----------------
__global__ __launch_bounds__(256) void kG(float* __restrict__ y) {
    int idx = blockIdx.x * 256 + threadIdx.x;
    int wpos = idx & 127;
    int h = (idx >> 7) & 63;
    int oc = (idx >> 13) & 127;
    int b0 = idx >> 20;
    int bh = b0 * 64 + h;
    int o = oc * 2;
    float v0 = g_outraw[(size_t)bh * 32768 + o * 128 + wpos];
    float v1 = g_outraw[(size_t)bh * 32768 + (o + 1) * 128 + wpos];
    y[idx] = (v0 * g_outScale[o] + g_outShift[o]) + (v1 * g_outScale[o + 1] + g_outShift[o + 1]);
}

// ---------------- launch ----------------
extern "C" void kernel_launch(void* const* d_in, const int* in_sizes, int n_in,
                              void* d_out, int out_size) {
    const float* x  = (const float*)d_in[0];
    const float* W  = (const float*)d_in[1];
    const float* gq = (const float*)d_in[2];
    const float* bq = (const float*)d_in[3];
    const float* re = (const float*)d_in[4];
    const float* gs = (const float*)d_in[5];
    // beta_sim (d_in[6]) cancels inside softmax — unused
    const float* go = (const float*)d_in[7];
    const float* bo = (const float*)d_in[8];
    float* y = (float*)d_out;

    const int SMEM_A = (16896 + 128 * 68) * 4;       // 102400
    const int SMEM_C = 20480 * 4;                    // 81920 -> 2 CTAs/SM
    const int SMEM_E = (23552 + 17408) * 4;          // 163840

    cudaFuncSetAttribute(kA, cudaFuncAttributeMaxDynamicSharedMemorySize, SMEM_A);
    cudaFuncSetAttribute(kC, cudaFuncAttributeMaxDynamicSharedMemorySize, SMEM_C);
    cudaFuncSetAttribute(kE, cudaFuncAttributeMaxDynamicSharedMemorySize, SMEM_E);

    kZero<<<1, 512>>>();
    kA<<<dim3(4, 128), 128, SMEM_A>>>(x, W);
    kBf<<<1, 256>>>(gq, bq);
    kC<<<dim3(16, 128), 512, SMEM_C>>>(re);
    kD<<<1, 64>>>(gs);
    kE<<<dim3(16, 128), 512, SMEM_E>>>(re);
    kF<<<1, 256>>>(go, bo);
    kG<<<8192, 256>>>(y);
}

// round 14
// speedup vs baseline: 1.1392x; 1.0349x over previous
#include <cuda_runtime.h>
#include <cuda_bf16.h>
#include <math.h>
#include <stdint.h>

#define EPSF 1e-5f

// ---------------- scratch (device globals) ----------------
__device__ float g_qkv[4194304];      // [128 bh][256 o][128 l]
__device__ float g_outraw[4194304];   // [128 bh][256 o][128 i]
__device__ float g_qkvStats[512];     // [256 ch][sum,sumsq]
__device__ float g_simStats[96];
__device__ float g_outStats[512];
__device__ float g_outScale[256];
__device__ float g_outShift[256];

__device__ __forceinline__ float warpSum(float v) {
#pragma unroll
    for (int o = 16; o > 0; o >>= 1) v += __shfl_xor_sync(0xffffffffu, v, o);
    return v;
}

// sum across the 8 lanes differing in bits 0..2 (tx groups in kA)
__device__ __forceinline__ float txSum(float v) {
    v += __shfl_xor_sync(0xffffffffu, v, 1);
    v += __shfl_xor_sync(0xffffffffu, v, 2);
    v += __shfl_xor_sync(0xffffffffu, v, 4);
    return v;
}

// reduce across lanes that differ only in bits 2..4 (rw groups, cl fixed)
__device__ __forceinline__ float rwSum(float v) {
    v += __shfl_xor_sync(0xffffffffu, v, 4);
    v += __shfl_xor_sync(0xffffffffu, v, 8);
    v += __shfl_xor_sync(0xffffffffu, v, 16);
    return v;
}

__device__ __forceinline__ uint32_t tf32r(float x) {
    uint32_t u;
    asm("cvt.rna.tf32.f32 %0, %1;" : "=r"(u) : "f"(x));
    return u;
}

__device__ __forceinline__ uint32_t packbf(float a, float b) {
    __nv_bfloat162 h = __floats2bfloat162_rn(a, b);
    return *(uint32_t*)&h;
}

__device__ __forceinline__ void mma8(float* c, const uint32_t* a, uint32_t b0, uint32_t b1) {
    asm volatile(
        "mma.sync.aligned.m16n8k8.row.col.f32.tf32.tf32.f32 "
        "{%0,%1,%2,%3},{%4,%5,%6,%7},{%8,%9},{%0,%1,%2,%3};\n"
        : "+f"(c[0]), "+f"(c[1]), "+f"(c[2]), "+f"(c[3])
        : "r"(a[0]), "r"(a[1]), "r"(a[2]), "r"(a[3]), "r"(b0), "r"(b1));
}

__device__ __forceinline__ void mma16(float* c, const uint32_t* a, uint32_t b0, uint32_t b1) {
    asm volatile(
        "mma.sync.aligned.m16n8k16.row.col.f32.bf16.bf16.f32 "
        "{%0,%1,%2,%3},{%4,%5,%6,%7},{%8,%9},{%0,%1,%2,%3};\n"
        : "+f"(c[0]), "+f"(c[1]), "+f"(c[2]), "+f"(c[3])
        : "r"(a[0]), "r"(a[1]), "r"(a[2]), "r"(a[3]), "r"(b0), "r"(b1));
}

// ---------------- Z: zero stat accumulators ----------------
__global__ void kZero() {
    int t = threadIdx.x;  // 512
    if (t < 96) g_simStats[t] = 0.f;
    g_outStats[t & 511] = 0.f;
    g_qkvStats[t & 511] = 0.f;
}

// ---------------- A: qkv GEMM, 8x8 thread tiles + fused BN stats ----------------
// grid (4, 128): bx = ot*2 + jh. 128 thr, smem ~100KB -> 2 CTAs/SM.
__global__ __launch_bounds__(128) void kA(const float* __restrict__ x,
                                          const float* __restrict__ W) {
    extern __shared__ float sm[];
    float* sa = sm;              // [128 k][132]  W^T tile (k-major)
    float* sb = sm + 16896;      // [128 k][68]   x tile (j-half)
    const int ot = blockIdx.x >> 1, jh = blockIdx.x & 1, bh = blockIdx.y;
    const int b0 = bh >> 6, h = bh & 63;
    const int t = threadIdx.x;

    for (int e = 0; e < 128; e++) {
        int idx = e * 128 + t;
        int r = idx >> 7, c = idx & 127;
        sa[c * 132 + r] = W[(ot * 128 + r) * 128 + c];
    }
    for (int e = 0; e < 64; e++) {
        int idx = e * 128 + t;
        int c = idx >> 6, l0 = idx & 63;
        sb[c * 68 + l0] = x[((b0 * 128 + c) * 64 + h) * 128 + jh * 64 + l0];
    }
    __syncthreads();

    const int ty = t >> 3, tx = t & 7;
    const int i0 = ty * 8, j0 = tx * 8;
    float acc[8][8];
#pragma unroll
    for (int u = 0; u < 8; u++)
#pragma unroll
        for (int v = 0; v < 8; v++) acc[u][v] = 0.f;

#pragma unroll 2
    for (int k = 0; k < 128; k++) {
        float4 A0 = *(const float4*)(sa + k * 132 + i0);
        float4 A1 = *(const float4*)(sa + k * 132 + i0 + 4);
        float4 B0 = *(const float4*)(sb + k * 68 + j0);
        float4 B1 = *(const float4*)(sb + k * 68 + j0 + 4);
        float a[8] = {A0.x, A0.y, A0.z, A0.w, A1.x, A1.y, A1.z, A1.w};
        float b[8] = {B0.x, B0.y, B0.z, B0.w, B1.x, B1.y, B1.z, B1.w};
#pragma unroll
        for (int u = 0; u < 8; u++)
#pragma unroll
            for (int v = 0; v < 8; v++) acc[u][v] += a[u] * b[v];
    }

    float* dst = g_qkv + (size_t)bh * 32768 + (size_t)(ot * 128) * 128 + jh * 64;
#pragma unroll
    for (int u = 0; u < 8; u++) {
        *(float4*)(dst + (i0 + u) * 128 + j0)     = make_float4(acc[u][0], acc[u][1], acc[u][2], acc[u][3]);
        *(float4*)(dst + (i0 + u) * 128 + j0 + 4) = make_float4(acc[u][4], acc[u][5], acc[u][6], acc[u][7]);
        float s = 0.f, s2 = 0.f;
#pragma unroll
        for (int v = 0; v < 8; v++) { s += acc[u][v]; s2 += acc[u][v] * acc[u][v]; }
        s = txSum(s);
        s2 = txSum(s2);
        if (tx == 0) {
            int ch = ot * 128 + i0 + u;
            atomicAdd(&g_qkvStats[ch * 2], s);
            atomicAdd(&g_qkvStats[ch * 2 + 1], s2);
        }
    }
}

// ---------------- C: fused qkv-BN + bf16 build + bf16 m16n8k16 qk + sim stats -------
// smem 80KB -> 2 CTAs/SM. grid (16, 128), 512 thr
__global__ __launch_bounds__(512, 2) void kC(const float* __restrict__ relemb,
                                             const float* __restrict__ gamma,
                                             const float* __restrict__ beta) {
    extern __shared__ float sm[];
    float* sreq = sm;            // [255][4]
    float* srek = sm + 1024;
    float* sq4  = sm + 2048;     // [128][4]
    float* sk4  = sm + 2560;
    uint32_t* sqe16 = (uint32_t*)(sm + 3072);    // [128 i][68 words], word = (m0,m1) bf16x2
    uint32_t* ske16 = (uint32_t*)(sm + 11776);   // [128 j][68 words]
    __shared__ float qscl[8], qsft[8];
    const int g = blockIdx.x, bh = blockIdx.y, t = threadIdx.x;
    const int lane = t & 31, w = t >> 5;

    if (t < 8) {
        int o = g * 16 + t;
        float S = g_qkvStats[o * 2], S2 = g_qkvStats[o * 2 + 1];
        float mean = S * (1.f / 16384.f);
        float var  = S2 * (1.f / 16384.f) - mean * mean;
        float sc = gamma[o] * rsqrtf(var + EPSF);
        qscl[t] = sc;
        qsft[t] = beta[o] - mean * sc;
    }
    __syncthreads();

    for (int n = t; n < 1020; n += 512) {
        int c = n & 3, d = n >> 2;
        sreq[n] = relemb[c * 255 + d];
        srek[n] = relemb[(4 + c) * 255 + d];
    }
    for (int n = t; n < 1024; n += 512) {
        int c8 = n >> 7, m = n & 127;
        int o = g * 16 + c8;
        float v = g_qkv[(size_t)bh * 32768 + o * 128 + m] * qscl[c8] + qsft[c8];
        if (c8 < 4) sq4[m * 4 + c8] = v; else sk4[m * 4 + c8 - 4] = v;
    }
    __syncthreads();

    // build: thread handles (m-pair mh, i)
    float sQE = 0.f, sQE2 = 0.f, sKE = 0.f, sKE2 = 0.f;
    for (int e = 0; e < 16; e++) {
        int idx = e * 512 + t;
        int mh = idx >> 7;        // 0..63
        int i  = idx & 127;
        int m0 = mh * 2;
        float4 qa = *(const float4*)(sq4 + 4 * m0);
        float4 qb = *(const float4*)(sq4 + 4 * m0 + 4);
        float4 ka = *(const float4*)(sk4 + 4 * m0);
        float4 kb = *(const float4*)(sk4 + 4 * m0 + 4);
        int d0 = m0 - i + 127;
        float4 rq0 = *(const float4*)(sreq + 4 * d0);
        float4 rq1 = *(const float4*)(sreq + 4 * d0 + 4);
        float4 rk0 = *(const float4*)(srek + 4 * d0);
        float4 rk1 = *(const float4*)(srek + 4 * d0 + 4);
        float qe0 = qa.x * rq0.x + qa.y * rq0.y + qa.z * rq0.z + qa.w * rq0.w;
        float qe1 = qb.x * rq1.x + qb.y * rq1.y + qb.z * rq1.z + qb.w * rq1.w;
        float ke0 = ka.x * rk0.x + ka.y * rk0.y + ka.z * rk0.z + ka.w * rk0.w;
        float ke1 = kb.x * rk1.x + kb.y * rk1.y + kb.z * rk1.z + kb.w * rk1.w;
        sQE += qe0 + qe1; sQE2 += qe0 * qe0 + qe1 * qe1;
        sKE += ke0 + ke1; sKE2 += ke0 * ke0 + ke1 * ke1;
        sqe16[i * 68 + mh] = packbf(qe0, qe1);
        ske16[i * 68 + mh] = packbf(ke0, ke1);
    }
    __syncthreads();

    // qk = qe^T * ke via bf16 m16n8k16. 16 warps, tile 32(i) x 32(j).
    const int i0w = (w >> 2) * 32, j0w = (w & 3) * 32;
    const int rw = lane >> 2, cl = lane & 3;
    float c[2][4][4];
#pragma unroll
    for (int ii = 0; ii < 2; ii++)
#pragma unroll
        for (int jj = 0; jj < 4; jj++)
#pragma unroll
            for (int u = 0; u < 4; u++) c[ii][jj][u] = 0.f;

    for (int kc = 0; kc < 8; kc++) {
        const int kw = kc * 8;
        uint32_t a[2][4];
#pragma unroll
        for (int ii = 0; ii < 2; ii++) {
            const uint32_t* base = sqe16 + (i0w + ii * 16 + rw) * 68 + kw + cl;
            a[ii][0] = base[0];
            a[ii][1] = base[8 * 68];
            a[ii][2] = base[4];
            a[ii][3] = base[8 * 68 + 4];
        }
#pragma unroll
        for (int jj = 0; jj < 4; jj++) {
            const uint32_t* bb = ske16 + (j0w + jj * 8 + rw) * 68 + kw + cl;
            uint32_t b0 = bb[0];
            uint32_t b1 = bb[4];
            mma16(c[0][jj], a[0], b0, b1);
            mma16(c[1][jj], a[1], b0, b1);
        }
    }

    float sQK = 0.f, sQK2 = 0.f;
#pragma unroll
    for (int ii = 0; ii < 2; ii++)
#pragma unroll
        for (int jj = 0; jj < 4; jj++)
#pragma unroll
            for (int u = 0; u < 4; u++) { float q = c[ii][jj][u]; sQK += q; sQK2 += q * q; }

    sQK = warpSum(sQK); sQK2 = warpSum(sQK2);
    sQE = warpSum(sQE); sQE2 = warpSum(sQE2);
    sKE = warpSum(sKE); sKE2 = warpSum(sKE2);
    float* red = sq4;  // reuse
    if (lane == 0) {
        red[w * 8 + 0] = sQK; red[w * 8 + 1] = sQK2;
        red[w * 8 + 2] = sQE; red[w * 8 + 3] = sQE2;
        red[w * 8 + 4] = sKE; red[w * 8 + 5] = sKE2;
    }
    __syncthreads();
    if (t < 6) {
        float tot = 0.f;
        for (int i = 0; i < 16; i++) tot += red[i * 8 + t];
        int ch = (t < 2) ? g : (t < 4) ? (16 + g) : (32 + g);
        atomicAdd(&g_simStats[ch * 2 + (t & 1)], tot);
    }
}

// ---------------- E: fused BN + qk MMA + in-register softmax + am/ame ----------------
// grid (16, 128), 512 thr
__global__ __launch_bounds__(512) void kE(const float* __restrict__ relemb,
                                          const float* __restrict__ gamma,
                                          const float* __restrict__ beta,
                                          const float* __restrict__ gamma_sim) {
    extern __shared__ float sm[];
    float* sreq = sm;            // [255][4]
    float* srek = sm + 1024;
    float* srva = sm + 2048;     // v rel ch 0..3 [d][4]
    float* srvb = sm + 3072;     // v rel ch 4..7 [d][4]
    float* sq4  = sm + 4096;     // [128][4]
    float* sk4  = sm + 4608;
    float* sv8  = sm + 5120;     // v all 8 ch [j][8] (tf32-rounded)
    float* schkA = sm + 6144;    // [128][4] row-chunk max
    float* schkB = sm + 6656;    // [128][4] row-chunk sum
    float* sqe  = sm + 7168;     // [128][136] tf32-rounded; aliased by ssim later
    float* ske  = sm + 24576;    // [128][136]; aliased by amePart later
    float* ssim = sqe;           // [128][133] final p (tf32-rounded)
    float* amePart = ske;        // [8 c][4 strip][128 i]
    __shared__ float qscl[16], qsft[16], sscale[3];
    const int g = blockIdx.x, bh = blockIdx.y, t = threadIdx.x;
    const int lane = t & 31, w = t >> 5;
    const int rw = lane >> 2, cl = lane & 3;

    if (t < 16) {
        int o = g * 16 + t;
        float S = g_qkvStats[o * 2], S2 = g_qkvStats[o * 2 + 1];
        float mean = S * (1.f / 16384.f);
        float var  = S2 * (1.f / 16384.f) - mean * mean;
        float sc = gamma[o] * rsqrtf(var + EPSF);
        qscl[t] = sc;
        qsft[t] = beta[o] - mean * sc;
    } else if (t < 19) {
        int idx = t - 16;                 // 0..2
        int ch = idx * 16 + g;
        const float N = 2097152.f;
        float S = g_simStats[ch * 2], S2 = g_simStats[ch * 2 + 1];
        float mean = S / N;
        float var = S2 / N - mean * mean;
        sscale[idx] = gamma_sim[ch] * rsqrtf(var + EPSF);
    }
    __syncthreads();

    for (int n = t; n < 1020; n += 512) {
        int c = n & 3, d = n >> 2;
        sreq[n] = relemb[c * 255 + d];
        srek[n] = relemb[(4 + c) * 255 + d];
        srva[n] = relemb[(8 + c) * 255 + d];
        srvb[n] = relemb[(12 + c) * 255 + d];
    }
    for (int n = t; n < 2048; n += 512) {
        int c8 = n >> 7, m = n & 127;
        int o = g * 16 + c8;
        float v = g_qkv[(size_t)bh * 32768 + o * 128 + m] * qscl[c8] + qsft[c8];
        if (c8 < 4)       sq4[m * 4 + c8] = v;
        else if (c8 < 8)  sk4[m * 4 + c8 - 4] = v;
        else              sv8[m * 8 + c8 - 8] = __uint_as_float(tf32r(v));
    }
    __syncthreads();

    for (int e = 0; e < 32; e++) {
        int idx = e * 512 + t;
        int m = idx >> 7, i = idx & 127;
        int d = m - i + 127;
        float4 qv = *(const float4*)(sq4 + 4 * m);
        float4 rq = *(const float4*)(sreq + 4 * d);
        float4 kv = *(const float4*)(sk4 + 4 * m);
        float4 rk = *(const float4*)(srek + 4 * d);
        float qe = qv.x * rq.x + qv.y * rq.y + qv.z * rq.z + qv.w * rq.w;
        float ke = kv.x * rk.x + kv.y * rk.y + kv.z * rk.z + kv.w * rk.w;
        sqe[m * 136 + i] = __uint_as_float(tf32r(qe));
        ske[m * 136 + i] = __uint_as_float(tf32r(ke));
    }
    __syncthreads();

    // qk MMA: 16 warps, 32x32 tiles, + combine into fragments
    const float a1 = sscale[0], a2 = sscale[1], a3 = sscale[2];
    const int i0w = (w >> 2) * 32, j0w = (w & 3) * 32;
    float c[2][4][4];
#pragma unroll
    for (int ii = 0; ii < 2; ii++)
#pragma unroll
        for (int jj = 0; jj < 4; jj++)
#pragma unroll
            for (int u = 0; u < 4; u++) c[ii][jj][u] = 0.f;

    for (int kc = 0; kc < 16; kc++) {
        const int k0 = kc * 8;
        uint32_t a[2][4];
#pragma unroll
        for (int ii = 0; ii < 2; ii++) {
            const float* base = sqe + (k0 + cl) * 136 + i0w + ii * 16 + rw;
            a[ii][0] = __float_as_uint(base[0]);
            a[ii][1] = __float_as_uint(base[8]);
            a[ii][2] = __float_as_uint(base[4 * 136]);
            a[ii][3] = __float_as_uint(base[4 * 136 + 8]);
        }
#pragma unroll
        for (int jj = 0; jj < 4; jj++) {
            const float* bb = ske + (k0 + cl) * 136 + j0w + jj * 8 + rw;
            uint32_t b0 = __float_as_uint(bb[0]);
            uint32_t b1 = __float_as_uint(bb[4 * 136]);
            mma8(c[0][jj], a[0], b0, b1);
            mma8(c[1][jj], a[1], b0, b1);
        }
    }

    // combine: sim = a1*qk + a2*qe + a3*ke at fragment coords
#pragma unroll
    for (int ii = 0; ii < 2; ii++)
#pragma unroll
        for (int jj = 0; jj < 4; jj++) {
            int ir0 = i0w + ii * 16 + rw;
            int jc = j0w + jj * 8 + 2 * cl;
            float2 q0 = *(const float2*)(sqe + ir0 * 136 + jc);
            float2 k0 = *(const float2*)(ske + ir0 * 136 + jc);
            float2 q1 = *(const float2*)(sqe + (ir0 + 8) * 136 + jc);
            float2 k1 = *(const float2*)(ske + (ir0 + 8) * 136 + jc);
            float* cc = c[ii][jj];
            cc[0] = a1 * cc[0] + a2 * q0.x + a3 * k0.x;
            cc[1] = a1 * cc[1] + a2 * q0.y + a3 * k0.y;
            cc[2] = a1 * cc[2] + a2 * q1.x + a3 * k1.x;
            cc[3] = a1 * cc[3] + a2 * q1.y + a3 * k1.y;
        }

    // ---- in-register softmax over j (rows live in fragments) ----
    // lane rows: r0=i0w+rw (ii0 lo), r1=+8 (ii0 hi), r2=+16 (ii1 lo), r3=+24 (ii1 hi)
    float mx[4];
#pragma unroll
    for (int r = 0; r < 4; r++) mx[r] = -1e30f;
#pragma unroll
    for (int jj = 0; jj < 4; jj++) {
        mx[0] = fmaxf(mx[0], fmaxf(c[0][jj][0], c[0][jj][1]));
        mx[1] = fmaxf(mx[1], fmaxf(c[0][jj][2], c[0][jj][3]));
        mx[2] = fmaxf(mx[2], fmaxf(c[1][jj][0], c[1][jj][1]));
        mx[3] = fmaxf(mx[3], fmaxf(c[1][jj][2], c[1][jj][3]));
    }
#pragma unroll
    for (int o = 1; o <= 2; o <<= 1)
#pragma unroll
        for (int r = 0; r < 4; r++)
            mx[r] = fmaxf(mx[r], __shfl_xor_sync(0xffffffffu, mx[r], o));
    if (cl == 0) {
        int jt = w & 3;
        schkA[(i0w + rw) * 4 + jt]      = mx[0];
        schkA[(i0w + rw + 8) * 4 + jt]  = mx[1];
        schkA[(i0w + rw + 16) * 4 + jt] = mx[2];
        schkA[(i0w + rw + 24) * 4 + jt] = mx[3];
    }
    __syncthreads();
    float gmx[4];
#pragma unroll
    for (int r = 0; r < 4; r++) {
        float4 m4 = *(const float4*)(schkA + (i0w + rw + r * 8) * 4);
        gmx[r] = fmaxf(fmaxf(m4.x, m4.y), fmaxf(m4.z, m4.w));
    }
    float sums[4] = {0.f, 0.f, 0.f, 0.f};
#pragma unroll
    for (int jj = 0; jj < 4; jj++) {
        c[0][jj][0] = __expf(c[0][jj][0] - gmx[0]);
        c[0][jj][1] = __expf(c[0][jj][1] - gmx[0]);
        sums[0] += c[0][jj][0] + c[0][jj][1];
        c[0][jj][2] = __expf(c[0][jj][2] - gmx[1]);
        c[0][jj][3] = __expf(c[0][jj][3] - gmx[1]);
        sums[1] += c[0][jj][2] + c[0][jj][3];
        c[1][jj][0] = __expf(c[1][jj][0] - gmx[2]);
        c[1][jj][1] = __expf(c[1][jj][1] - gmx[2]);
        sums[2] += c[1][jj][0] + c[1][jj][1];
        c[1][jj][2] = __expf(c[1][jj][2] - gmx[3]);
        c[1][jj][3] = __expf(c[1][jj][3] - gmx[3]);
        sums[3] += c[1][jj][2] + c[1][jj][3];
    }
#pragma unroll
    for (int o = 1; o <= 2; o <<= 1)
#pragma unroll
        for (int r = 0; r < 4; r++)
            sums[r] += __shfl_xor_sync(0xffffffffu, sums[r], o);
    if (cl == 0) {
        int jt = w & 3;
        schkB[(i0w + rw) * 4 + jt]      = sums[0];
        schkB[(i0w + rw + 8) * 4 + jt]  = sums[1];
        schkB[(i0w + rw + 16) * 4 + jt] = sums[2];
        schkB[(i0w + rw + 24) * 4 + jt] = sums[3];
    }
    __syncthreads();
    float inv[4];
#pragma unroll
    for (int r = 0; r < 4; r++) {
        float4 s4 = *(const float4*)(schkB + (i0w + rw + r * 8) * 4);
        inv[r] = 1.f / (s4.x + s4.y + s4.z + s4.w);
    }
    // write final p (tf32-rounded) to ssim — SCALAR stores (pitch 133 is odd; float2
    // stores at odd rows are misaligned -> R13 crash)
#pragma unroll
    for (int ii = 0; ii < 2; ii++)
#pragma unroll
        for (int jj = 0; jj < 4; jj++) {
            int ir0 = i0w + ii * 16 + rw;
            int jc = j0w + jj * 8 + 2 * cl;
            float* cc = c[ii][jj];
            float ivl = inv[ii * 2], ivh = inv[ii * 2 + 1];
            ssim[ir0 * 133 + jc]           = __uint_as_float(tf32r(cc[0] * ivl));
            ssim[ir0 * 133 + jc + 1]       = __uint_as_float(tf32r(cc[1] * ivl));
            ssim[(ir0 + 8) * 133 + jc]     = __uint_as_float(tf32r(cc[2] * ivh));
            ssim[(ir0 + 8) * 133 + jc + 1] = __uint_as_float(tf32r(cc[3] * ivh));
        }
    __syncthreads();

    // ame strips: thread owns (i, strip of 32 j), all 8 channels -> partials to smem
    {
        const int i = t & 127, s = t >> 7;
        float accE[8] = {0.f, 0.f, 0.f, 0.f, 0.f, 0.f, 0.f, 0.f};
        const int jb = s * 32;
        for (int jj = 0; jj < 32; jj++) {
            int j = jb + jj;
            float p = ssim[i * 133 + j];
            int d = i - j + 127;
            float4 ra = *(const float4*)(srva + 4 * d);
            float4 rb = *(const float4*)(srvb + 4 * d);
            accE[0] += p * ra.x; accE[1] += p * ra.y; accE[2] += p * ra.z; accE[3] += p * ra.w;
            accE[4] += p * rb.x; accE[5] += p * rb.y; accE[6] += p * rb.z; accE[7] += p * rb.w;
        }
        __syncthreads();   // ske reads fully done earlier; amePart aliases ske
#pragma unroll
        for (int ch = 0; ch < 8; ch++)
            amePart[ch * 512 + s * 128 + i] = accE[ch];
    }
    __syncthreads();

    float* dst = g_outraw + (size_t)bh * 32768;
    if (w < 8) {
        // am via tf32 MMA: A = P (ssim, pre-rounded), B = v (sv8, pre-rounded)
        const int i0 = w * 16;
        float ca[4] = {0.f, 0.f, 0.f, 0.f};
        for (int kc = 0; kc < 16; kc++) {
            const int k0 = kc * 8;
            const float* pr0 = ssim + (i0 + rw) * 133 + k0 + cl;
            const float* pr1 = pr0 + 8 * 133;
            uint32_t a[4];
            a[0] = __float_as_uint(pr0[0]);
            a[1] = __float_as_uint(pr1[0]);
            a[2] = __float_as_uint(pr0[4]);
            a[3] = __float_as_uint(pr1[4]);
            uint32_t b0 = __float_as_uint(sv8[(k0 + cl) * 8 + rw]);
            uint32_t b1 = __float_as_uint(sv8[(k0 + cl + 4) * 8 + rw]);
            mma8(ca, a, b0, b1);
        }
        const int i1 = i0 + rw, i2 = i0 + rw + 8;
        const int ch0 = 2 * cl, ch1 = 2 * cl + 1;
        const int o0 = g * 16 + 2 * ch0, o1 = g * 16 + 2 * ch1;
        dst[o0 * 128 + i1] = ca[0];
        dst[o1 * 128 + i1] = ca[1];
        dst[o0 * 128 + i2] = ca[2];
        dst[o1 * 128 + i2] = ca[3];
        float s0 = ca[0] + ca[2], s02 = ca[0] * ca[0] + ca[2] * ca[2];
        float s1 = ca[1] + ca[3], s12 = ca[1] * ca[1] + ca[3] * ca[3];
        s0 = rwSum(s0); s02 = rwSum(s02); s1 = rwSum(s1); s12 = rwSum(s12);
        if (rw == 0) {
            atomicAdd(&g_outStats[o0 * 2], s0);
            atomicAdd(&g_outStats[o0 * 2 + 1], s02);
            atomicAdd(&g_outStats[o1 * 2], s1);
            atomicAdd(&g_outStats[o1 * 2 + 1], s12);
        }
    } else {
        // ame reduce: warp handles one channel; lane covers 4 consecutive i
        const int ch = w - 8;
        const int iB = lane * 4;
        float4 v0 = *(const float4*)(amePart + ch * 512 + 0 * 128 + iB);
        float4 v1 = *(const float4*)(amePart + ch * 512 + 1 * 128 + iB);
        float4 v2 = *(const float4*)(amePart + ch * 512 + 2 * 128 + iB);
        float4 v3 = *(const float4*)(amePart + ch * 512 + 3 * 128 + iB);
        float4 r4 = make_float4(v0.x + v1.x + v2.x + v3.x,
                                v0.y + v1.y + v2.y + v3.y,
                                v0.z + v1.z + v2.z + v3.z,
                                v0.w + v1.w + v2.w + v3.w);
        const int o = g * 16 + 2 * ch + 1;
        *(float4*)(dst + o * 128 + iB) = r4;
        float sE = r4.x + r4.y + r4.z + r4.w;
        float sE2 = r4.x * r4.x + r4.y * r4.y + r4.z * r4.z + r4.w * r4.w;
        sE = warpSum(sE); sE2 = warpSum(sE2);
        if (lane == 0) {
            atomicAdd(&g_outStats[o * 2], sE);
            atomicAdd(&g_outStats[o * 2 + 1], sE2);
        }
    }
}

// ---------------- F: finalize out BN params ----------------
__global__ void kF(const float* __restrict__ gamma_out, const float* __restrict__ beta_out) {
    int o = threadIdx.x;  // 256
    const float N = 16384.f;
    float S = g_outStats[o * 2], S2 = g_outStats[o * 2 + 1];
    float mean = S / N;
    float var = S2 / N - mean * mean;
    float sc = gamma_out[o] * rsqrtf(var + EPSF);
    g_outScale[o] = sc;
    g_outShift[o] = beta_out[o] - mean * sc;
}

// ---------------- G: y = bn(out)[2oc] + bn(out)[2oc+1] ----------------
__global__ __launch_bounds__(256) void kG(float* __restrict__ y) {
    int idx = blockIdx.x * 256 + threadIdx.x;
    int wpos = idx & 127;
    int h = (idx >> 7) & 63;
    int oc = (idx >> 13) & 127;
    int b0 = idx >> 20;
    int bh = b0 * 64 + h;
    int o = oc * 2;
    float v0 = g_outraw[(size_t)bh * 32768 + o * 128 + wpos];
    float v1 = g_outraw[(size_t)bh * 32768 + (o + 1) * 128 + wpos];
    y[idx] = (v0 * g_outScale[o] + g_outShift[o]) + (v1 * g_outScale[o + 1] + g_outShift[o + 1]);
}

// ---------------- launch ----------------
extern "C" void kernel_launch(void* const* d_in, const int* in_sizes, int n_in,
                              void* d_out, int out_size) {
    const float* x  = (const float*)d_in[0];
    const float* W  = (const float*)d_in[1];
    const float* gq = (const float*)d_in[2];
    const float* bq = (const float*)d_in[3];
    const float* re = (const float*)d_in[4];
    const float* gs = (const float*)d_in[5];
    // beta_sim (d_in[6]) cancels inside softmax — unused
    const float* go = (const float*)d_in[7];
    const float* bo = (const float*)d_in[8];
    float* y = (float*)d_out;

    const int SMEM_A = (16896 + 128 * 68) * 4;       // 102400
    const int SMEM_C = 20480 * 4;                    // 81920 -> 2 CTAs/SM
    const int SMEM_E = (24576 + 17408) * 4;          // 167936

    cudaFuncSetAttribute(kA, cudaFuncAttributeMaxDynamicSharedMemorySize, SMEM_A);
    cudaFuncSetAttribute(kC, cudaFuncAttributeMaxDynamicSharedMemorySize, SMEM_C);
    cudaFuncSetAttribute(kE, cudaFuncAttributeMaxDynamicSharedMemorySize, SMEM_E);

    kZero<<<1, 512>>>();
    kA<<<dim3(4, 128), 128, SMEM_A>>>(x, W);
    kC<<<dim3(16, 128), 512, SMEM_C>>>(re, gq, bq);
    kE<<<dim3(16, 128), 512, SMEM_E>>>(re, gq, bq, gs);
    kF<<<1, 256>>>(go, bo);
    kG<<<8192, 256>>>(y);
}